// round 1
// baseline (speedup 1.0000x reference)
#include <cuda_runtime.h>

// Problem constants
static constexpr int BB   = 4;
static constexpr int S    = 1024;
static constexpr int F    = 128;
static constexpr int HH   = 512;
static constexpr int NHD  = 8;
static constexpr int DH   = 64;
static constexpr int OO   = 128;
static constexpr int ROWS = BB * S;         // 4096

// Scratch (device globals; no runtime allocation allowed)
__device__ float g_buf1[ROWS * HH];
__device__ float g_buf2[ROWS * HH];
__device__ float g_Kh[ROWS * HH];           // [b][h][i][d]
__device__ float g_Qh[ROWS * HH];
__device__ float g_Vh[ROWS * HH];
__device__ float g_E[(long)BB * NHD * S * S];  // [z=b*8+h][j][i], 134 MB
__device__ float g_rd[(long)BB * S * S];       // [b][j][i] reciprocal head-denominator
__device__ float g_attn[ROWS * HH];            // [b][j][f = d*8+h]

// ---------------------------------------------------------------------------
// Double-buffered 128x128x8 SGEMM with fused bias (+ optional ReLU).
// C[M,N] = A[M,K] @ B[K,N] + bias, row-major. M%128==0, N%128==0, K%8==0.
// ---------------------------------------------------------------------------
__global__ __launch_bounds__(256) void sgemm_bias(
    const float* __restrict__ A, const float* __restrict__ B,
    const float* __restrict__ bias, float* __restrict__ C,
    int M, int N, int K, int relu)
{
    __shared__ float As[2][8][128];
    __shared__ float Bs[2][8][128];

    const int tid = threadIdx.x;
    const int bx = blockIdx.x, by = blockIdx.y;

    const int ar = tid >> 1;          // 0..127
    const int ac = (tid & 1) << 2;    // 0 or 4
    const int br = tid >> 5;          // 0..7
    const int bc = (tid & 31) << 2;   // 0..124

    const float* Ap = A + (long)(by * 128 + ar) * K + ac;
    const float* Bp = B + (long)br * N + bx * 128 + bc;

    float4 a4 = *(const float4*)Ap;
    float4 b4 = *(const float4*)Bp;
    As[0][ac + 0][ar] = a4.x; As[0][ac + 1][ar] = a4.y;
    As[0][ac + 2][ar] = a4.z; As[0][ac + 3][ar] = a4.w;
    *(float4*)&Bs[0][br][bc] = b4;
    __syncthreads();

    const int ty = tid >> 4, tx = tid & 15;

    float acc[8][8];
#pragma unroll
    for (int m = 0; m < 8; m++)
#pragma unroll
        for (int n = 0; n < 8; n++) acc[m][n] = 0.f;

    const int nt = K >> 3;
    int buf = 0;
    for (int kt = 0; kt < nt; kt++) {
        if (kt + 1 < nt) {
            a4 = *(const float4*)(Ap + (kt + 1) * 8);
            b4 = *(const float4*)(Bp + (long)(kt + 1) * 8 * N);
        }
#pragma unroll
        for (int k = 0; k < 8; k++) {
            float af[8], bf[8];
            *(float4*)&af[0] = *(const float4*)&As[buf][k][ty * 8];
            *(float4*)&af[4] = *(const float4*)&As[buf][k][ty * 8 + 4];
            *(float4*)&bf[0] = *(const float4*)&Bs[buf][k][tx * 8];
            *(float4*)&bf[4] = *(const float4*)&Bs[buf][k][tx * 8 + 4];
#pragma unroll
            for (int m = 0; m < 8; m++)
#pragma unroll
                for (int n = 0; n < 8; n++) acc[m][n] += af[m] * bf[n];
        }
        if (kt + 1 < nt) {
            buf ^= 1;
            As[buf][ac + 0][ar] = a4.x; As[buf][ac + 1][ar] = a4.y;
            As[buf][ac + 2][ar] = a4.z; As[buf][ac + 3][ar] = a4.w;
            *(float4*)&Bs[buf][br][bc] = b4;
            __syncthreads();
        }
    }

    float bb[8];
#pragma unroll
    for (int n = 0; n < 8; n++) bb[n] = bias[bx * 128 + tx * 8 + n];

#pragma unroll
    for (int m = 0; m < 8; m++) {
        const int row = by * 128 + ty * 8 + m;
        float o[8];
#pragma unroll
        for (int n = 0; n < 8; n++) {
            float v = acc[m][n] + bb[n];
            o[n] = relu ? fmaxf(v, 0.f) : v;
        }
        float* cp = C + (long)row * N + bx * 128 + tx * 8;
        *(float4*)(cp + 0) = make_float4(o[0], o[1], o[2], o[3]);
        *(float4*)(cp + 4) = make_float4(o[4], o[5], o[6], o[7]);
    }
}

// ---------------------------------------------------------------------------
// Permute MLP output [row=b*1024+i][f=d*8+h] -> [b][h][i][d]
// ---------------------------------------------------------------------------
__global__ __launch_bounds__(256) void permute_kernel(
    const float* __restrict__ X, float* __restrict__ Y)
{
    const int gid = blockIdx.x * 256 + threadIdx.x;   // ROWS*DH = 262144
    const int row = gid >> 6;
    const int d   = gid & 63;
    const int b   = row >> 10, i = row & 1023;
    const float4 x0 = *(const float4*)(X + (long)row * 512 + d * 8);
    const float4 x1 = *(const float4*)(X + (long)row * 512 + d * 8 + 4);
    const int base = ((b * 8) * 1024 + i) * 64 + d;   // h stride = 65536
    Y[base + 0 * 65536] = x0.x;
    Y[base + 1 * 65536] = x0.y;
    Y[base + 2 * 65536] = x0.z;
    Y[base + 3 * 65536] = x0.w;
    Y[base + 4 * 65536] = x1.x;
    Y[base + 5 * 65536] = x1.y;
    Y[base + 6 * 65536] = x1.z;
    Y[base + 7 * 65536] = x1.w;
}

// ---------------------------------------------------------------------------
// Phase A1: distance-GEMM.  E[z][j][i] = exp(-0.5 * (sum_d |Q[z,j,d]-K[z,i,d]|)^2)
// 128x128 tile per block, K-dim = 64 dims in 4 chunks of 16.
// ---------------------------------------------------------------------------
__global__ __launch_bounds__(256) void dist_exp_kernel(
    const float* __restrict__ Qh, const float* __restrict__ Kh,
    float* __restrict__ E)
{
    __shared__ float Qs[16][128];
    __shared__ float Ks[16][128];

    const int z   = blockIdx.z;
    const int tid = threadIdx.x;
    const int r   = tid >> 1;            // tile row 0..127
    const int dc  = (tid & 1) << 3;      // 0 or 8
    const int ty  = tid >> 4, tx = tid & 15;

    const float* Qp = Qh + (long)(z * 1024 + blockIdx.y * 128 + r) * 64 + dc;
    const float* Kp = Kh + (long)(z * 1024 + blockIdx.x * 128 + r) * 64 + dc;

    float acc[8][8];
#pragma unroll
    for (int m = 0; m < 8; m++)
#pragma unroll
        for (int n = 0; n < 8; n++) acc[m][n] = 0.f;

    for (int kt = 0; kt < 4; kt++) {
        const float4 q0 = *(const float4*)(Qp + kt * 16);
        const float4 q1 = *(const float4*)(Qp + kt * 16 + 4);
        const float4 k0 = *(const float4*)(Kp + kt * 16);
        const float4 k1 = *(const float4*)(Kp + kt * 16 + 4);
        if (kt) __syncthreads();
        Qs[dc + 0][r] = q0.x; Qs[dc + 1][r] = q0.y; Qs[dc + 2][r] = q0.z; Qs[dc + 3][r] = q0.w;
        Qs[dc + 4][r] = q1.x; Qs[dc + 5][r] = q1.y; Qs[dc + 6][r] = q1.z; Qs[dc + 7][r] = q1.w;
        Ks[dc + 0][r] = k0.x; Ks[dc + 1][r] = k0.y; Ks[dc + 2][r] = k0.z; Ks[dc + 3][r] = k0.w;
        Ks[dc + 4][r] = k1.x; Ks[dc + 5][r] = k1.y; Ks[dc + 6][r] = k1.z; Ks[dc + 7][r] = k1.w;
        __syncthreads();
#pragma unroll
        for (int k = 0; k < 16; k++) {
            float qf[8], kf[8];
            *(float4*)&qf[0] = *(const float4*)&Qs[k][ty * 8];
            *(float4*)&qf[4] = *(const float4*)&Qs[k][ty * 8 + 4];
            *(float4*)&kf[0] = *(const float4*)&Ks[k][tx * 8];
            *(float4*)&kf[4] = *(const float4*)&Ks[k][tx * 8 + 4];
#pragma unroll
            for (int m = 0; m < 8; m++)
#pragma unroll
                for (int n = 0; n < 8; n++) acc[m][n] += fabsf(qf[m] - kf[n]);
        }
    }

    const long base = ((long)(z * 1024 + blockIdx.y * 128 + ty * 8)) * 1024
                    + blockIdx.x * 128 + tx * 8;
#pragma unroll
    for (int m = 0; m < 8; m++) {
        float o[8];
#pragma unroll
        for (int n = 0; n < 8; n++) {
            const float d = acc[m][n];
            o[n] = __expf(-0.5f * d * d);
        }
        float* ep = &g_E[0] + base + (long)m * 1024;
        (void)ep;
        *(float4*)(E + base + (long)m * 1024 + 0) = make_float4(o[0], o[1], o[2], o[3]);
        *(float4*)(E + base + (long)m * 1024 + 4) = make_float4(o[4], o[5], o[6], o[7]);
    }
}

// ---------------------------------------------------------------------------
// Phase A2: rdenom[b][j][i] = 1 / sum_h E[b*8+h][j][i]   (float4 vectorized)
// ---------------------------------------------------------------------------
__global__ __launch_bounds__(256) void denom_kernel(
    const float* __restrict__ E, float* __restrict__ rd)
{
    const int gid = blockIdx.x * 256 + threadIdx.x;  // 1048576 float4s
    const int b   = gid >> 18;
    const int rem = gid & ((1 << 18) - 1);
    const float4* Ep = (const float4*)E;
    float4 s = make_float4(0.f, 0.f, 0.f, 0.f);
#pragma unroll
    for (int h = 0; h < 8; h++) {
        const float4 v = Ep[(((long)(b * 8 + h)) << 18) + rem];
        s.x += v.x; s.y += v.y; s.z += v.z; s.w += v.w;
    }
    ((float4*)rd)[gid] = make_float4(1.f / s.x, 1.f / s.y, 1.f / s.z, 1.f / s.w);
}

// ---------------------------------------------------------------------------
// Phase B: out[b][j][d*8+h] = sum_i (E[z][j][i]*rd[b][j][i]) * V[z][i][d]
// Batched GEMM M=1024(j) N=64(d) K=1024(i), normalization fused in A-load.
// ---------------------------------------------------------------------------
__global__ __launch_bounds__(256) void attn_v_kernel(
    const float* __restrict__ E, const float* __restrict__ rd,
    const float* __restrict__ Vh, float* __restrict__ Oo)
{
    __shared__ float As[16][128];
    __shared__ float Vs[16][64];

    const int z = blockIdx.z, b = z >> 3, h = z & 7;
    const int tid = threadIdx.x;
    const int ar = tid >> 1, ac = (tid & 1) << 3;     // A: row, i-col base
    const int vr = tid >> 4, vc = (tid & 15) << 2;    // V: i-row, d-col
    const int ty = tid >> 4, tx = tid & 15;

    const float* Ep = E  + ((long)(z * 1024 + blockIdx.y * 128 + ar)) * 1024 + ac;
    const float* Rp = rd + ((long)(b * 1024 + blockIdx.y * 128 + ar)) * 1024 + ac;
    const float* Vp = Vh + (long)(z * 1024 + vr) * 64 + vc;

    float acc[8][4];
#pragma unroll
    for (int m = 0; m < 8; m++)
#pragma unroll
        for (int n = 0; n < 4; n++) acc[m][n] = 0.f;

    for (int kt = 0; kt < 64; kt++) {
        const float4 e0 = *(const float4*)(Ep + kt * 16);
        const float4 e1 = *(const float4*)(Ep + kt * 16 + 4);
        const float4 r0 = *(const float4*)(Rp + kt * 16);
        const float4 r1 = *(const float4*)(Rp + kt * 16 + 4);
        const float4 v4 = *(const float4*)(Vp + (long)kt * 16 * 64);
        if (kt) __syncthreads();
        As[ac + 0][ar] = e0.x * r0.x; As[ac + 1][ar] = e0.y * r0.y;
        As[ac + 2][ar] = e0.z * r0.z; As[ac + 3][ar] = e0.w * r0.w;
        As[ac + 4][ar] = e1.x * r1.x; As[ac + 5][ar] = e1.y * r1.y;
        As[ac + 6][ar] = e1.z * r1.z; As[ac + 7][ar] = e1.w * r1.w;
        *(float4*)&Vs[vr][vc] = v4;
        __syncthreads();
#pragma unroll
        for (int k = 0; k < 16; k++) {
            float af[8], vf[4];
            *(float4*)&af[0] = *(const float4*)&As[k][ty * 8];
            *(float4*)&af[4] = *(const float4*)&As[k][ty * 8 + 4];
            *(float4*)&vf[0] = *(const float4*)&Vs[k][tx * 4];
#pragma unroll
            for (int m = 0; m < 8; m++)
#pragma unroll
                for (int n = 0; n < 4; n++) acc[m][n] += af[m] * vf[n];
        }
    }

    const int j0 = blockIdx.y * 128 + ty * 8;
#pragma unroll
    for (int m = 0; m < 8; m++) {
        const int j = j0 + m;
        float* op = Oo + (long)(b * 1024 + j) * 512 + h;
#pragma unroll
        for (int n = 0; n < 4; n++) op[(tx * 4 + n) * 8] = acc[m][n];
    }
}

// ---------------------------------------------------------------------------
extern "C" void kernel_launch(void* const* d_in, const int* in_sizes, int n_in,
                              void* d_out, int out_size)
{
    const float* KEY   = (const float*)d_in[0];
    const float* VALUE = (const float*)d_in[1];
    const float* QUERY = (const float*)d_in[2];

    float *buf1, *buf2, *Kh, *Qh, *Vh, *E, *rd, *attn;
    cudaGetSymbolAddress((void**)&buf1, g_buf1);
    cudaGetSymbolAddress((void**)&buf2, g_buf2);
    cudaGetSymbolAddress((void**)&Kh,   g_Kh);
    cudaGetSymbolAddress((void**)&Qh,   g_Qh);
    cudaGetSymbolAddress((void**)&Vh,   g_Vh);
    cudaGetSymbolAddress((void**)&E,    g_E);
    cudaGetSymbolAddress((void**)&rd,   g_rd);
    cudaGetSymbolAddress((void**)&attn, g_attn);

    const dim3 blk(256);
    const dim3 gm(HH / 128, ROWS / 128);   // (4, 32)

    auto run_mlp = [&](const float* in, int base, float* out) {
        sgemm_bias<<<gm, blk>>>(in,   (const float*)d_in[base + 0],
                                (const float*)d_in[base + 1], buf1, ROWS, HH, F, 1);
        sgemm_bias<<<gm, blk>>>(buf1, (const float*)d_in[base + 2],
                                (const float*)d_in[base + 3], buf2, ROWS, HH, HH, 1);
        sgemm_bias<<<gm, blk>>>(buf2, (const float*)d_in[base + 4],
                                (const float*)d_in[base + 5], buf1, ROWS, HH, HH, 0);
        permute_kernel<<<ROWS * DH / 256, blk>>>(buf1, out);
    };

    run_mlp(KEY,   3,  Kh);
    run_mlp(QUERY, 9,  Qh);
    run_mlp(VALUE, 15, Vh);

    dist_exp_kernel<<<dim3(8, 8, 32), blk>>>(Qh, Kh, E);
    denom_kernel<<<4096, blk>>>(E, rd);
    attn_v_kernel<<<dim3(1, 8, 32), blk>>>(E, rd, Vh, attn);

    sgemm_bias<<<dim3(OO / 128, ROWS / 128), blk>>>(
        attn, (const float*)d_in[21], (const float*)d_in[22],
        (float*)d_out, ROWS, OO, HH, 0);
}

// round 2
// speedup vs baseline: 1.0055x; 1.0055x over previous
#include <cuda_runtime.h>

// Problem constants
static constexpr int BB   = 4;
static constexpr int S    = 1024;
static constexpr int F    = 128;
static constexpr int HH   = 512;
static constexpr int NHD  = 8;
static constexpr int DH   = 64;
static constexpr int OO   = 128;
static constexpr int ROWS = BB * S;         // 4096

// Scratch (device globals; no runtime allocation allowed)
__device__ float g_buf1[ROWS * HH];
__device__ float g_buf2[ROWS * HH];
__device__ float g_Kh[ROWS * HH];           // [b][h][i][d]
__device__ float g_Qh[ROWS * HH];
__device__ float g_Vh[ROWS * HH];
__device__ float g_E[(long)BB * NHD * S * S];  // [z=b*8+h][j][i]
__device__ float g_rd[(long)BB * S * S];       // [b][j][i] reciprocal head-denominator
__device__ float g_attn[ROWS * HH];            // [b][j][f = d*8+h]

// ---------------- packed f32x2 helpers ----------------
typedef unsigned long long u64;

__device__ __forceinline__ u64 dup2(float a) {
    u64 r;
    asm("mov.b64 %0, {%1, %1};" : "=l"(r) : "r"(__float_as_uint(a)));
    return r;
}
__device__ __forceinline__ void ffma2(u64& c, u64 a, u64 b) {
    asm("fma.rn.f32x2 %0, %1, %2, %0;" : "+l"(c) : "l"(a), "l"(b));
}
__device__ __forceinline__ u64 add2(u64 a, u64 b) {
    u64 d;
    asm("add.rn.f32x2 %0, %1, %2;" : "=l"(d) : "l"(a), "l"(b));
    return d;
}
__device__ __forceinline__ u64 abs2(u64 a) {
    u64 d;
    asm("and.b64 %0, %1, 0x7FFFFFFF7FFFFFFF;" : "=l"(d) : "l"(a));
    return d;
}
__device__ __forceinline__ void unpk2(float& lo, float& hi, u64 v) {
    unsigned int l, h;
    asm("mov.b64 {%0, %1}, %2;" : "=r"(l), "=r"(h) : "l"(v));
    lo = __uint_as_float(l);
    hi = __uint_as_float(h);
}

// ---------------------------------------------------------------------------
// Double-buffered 128x128x8 SGEMM with fused bias (+ optional ReLU) and
// optional fused head-split permute epilogue. FFMA2 (f32x2) inner product.
// C[M,N] = A[M,K] @ B[K,N] + bias, row-major. M%128==0, N%128==0, K%8==0.
// permute: write to Y[((b*8+h)*1024+i)*64+d] with f = d*8+h, row = b*1024+i.
// ---------------------------------------------------------------------------
__global__ __launch_bounds__(256) void sgemm_bias_x2(
    const float* __restrict__ A, const float* __restrict__ B,
    const float* __restrict__ bias, float* __restrict__ C,
    int M, int N, int K, int relu, int permute)
{
    __shared__ float As[2][8][128];
    __shared__ float Bs[2][8][128];

    const int tid = threadIdx.x;
    const int bx = blockIdx.x, by = blockIdx.y;

    const int ar = tid >> 1;          // 0..127
    const int ac = (tid & 1) << 2;    // 0 or 4
    const int br = tid >> 5;          // 0..7
    const int bc = (tid & 31) << 2;   // 0..124

    const float* Ap = A + (long)(by * 128 + ar) * K + ac;
    const float* Bp = B + (long)br * N + bx * 128 + bc;

    float4 a4 = *(const float4*)Ap;
    float4 b4 = *(const float4*)Bp;
    As[0][ac + 0][ar] = a4.x; As[0][ac + 1][ar] = a4.y;
    As[0][ac + 2][ar] = a4.z; As[0][ac + 3][ar] = a4.w;
    *(float4*)&Bs[0][br][bc] = b4;
    __syncthreads();

    const int ty = tid >> 4, tx = tid & 15;

    u64 acc2[8][4];
#pragma unroll
    for (int m = 0; m < 8; m++)
#pragma unroll
        for (int n = 0; n < 4; n++) acc2[m][n] = 0ULL;

    const int nt = K >> 3;
    int buf = 0;
    for (int kt = 0; kt < nt; kt++) {
        if (kt + 1 < nt) {
            a4 = *(const float4*)(Ap + (kt + 1) * 8);
            b4 = *(const float4*)(Bp + (long)(kt + 1) * 8 * N);
        }
#pragma unroll
        for (int k = 0; k < 8; k++) {
            float af[8];
            u64 b2[4];
            *(float4*)&af[0] = *(const float4*)&As[buf][k][ty * 8];
            *(float4*)&af[4] = *(const float4*)&As[buf][k][ty * 8 + 4];
            *(ulonglong2*)&b2[0] = *(const ulonglong2*)&Bs[buf][k][tx * 8];
            *(ulonglong2*)&b2[2] = *(const ulonglong2*)&Bs[buf][k][tx * 8 + 4];
#pragma unroll
            for (int m = 0; m < 8; m++) {
                const u64 a2 = dup2(af[m]);
#pragma unroll
                for (int n = 0; n < 4; n++) ffma2(acc2[m][n], a2, b2[n]);
            }
        }
        if (kt + 1 < nt) {
            buf ^= 1;
            As[buf][ac + 0][ar] = a4.x; As[buf][ac + 1][ar] = a4.y;
            As[buf][ac + 2][ar] = a4.z; As[buf][ac + 3][ar] = a4.w;
            *(float4*)&Bs[buf][br][bc] = b4;
            __syncthreads();
        }
    }

    float bb[8];
#pragma unroll
    for (int n = 0; n < 8; n++) bb[n] = bias[bx * 128 + tx * 8 + n];

#pragma unroll
    for (int m = 0; m < 8; m++) {
        const int row = by * 128 + ty * 8 + m;
        float o[8];
#pragma unroll
        for (int n = 0; n < 4; n++) {
            float lo, hi;
            unpk2(lo, hi, acc2[m][n]);
            float v0 = lo + bb[2 * n], v1 = hi + bb[2 * n + 1];
            o[2 * n]     = relu ? fmaxf(v0, 0.f) : v0;
            o[2 * n + 1] = relu ? fmaxf(v1, 0.f) : v1;
        }
        if (permute) {
            // row = b*1024 + i ; f = bx*128 + tx*8 + n -> h = n, d = bx*16+tx
            const int b = row >> 10, i = row & 1023;
            const int d = bx * 16 + tx;
            float* yp = C + ((long)(b * 8) * 1024 + i) * 64 + d;
#pragma unroll
            for (int n = 0; n < 8; n++) yp[n * 65536] = o[n];
        } else {
            float* cp = C + (long)row * N + bx * 128 + tx * 8;
            *(float4*)(cp + 0) = make_float4(o[0], o[1], o[2], o[3]);
            *(float4*)(cp + 4) = make_float4(o[4], o[5], o[6], o[7]);
        }
    }
}

// ---------------------------------------------------------------------------
// Phase A1: distance-GEMM.  E[z][j][i] = exp(-0.5 * (sum_d |Q[z,j,d]-K[z,i,d]|)^2)
// f32x2: Q stored duplicated in pairs, K stored negated; abs via alu-pipe and.b64.
// ---------------------------------------------------------------------------
__global__ __launch_bounds__(256) void dist_exp_x2(
    const float* __restrict__ Qh, const float* __restrict__ Kh,
    float* __restrict__ E)
{
    __shared__ float Qs[16][256];   // duplicated: Qs[k][2m] == Qs[k][2m+1]
    __shared__ float Ks[16][128];   // negated

    const int z   = blockIdx.z;
    const int tid = threadIdx.x;
    const int r   = tid >> 1;            // tile row 0..127
    const int dc  = (tid & 1) << 3;      // 0 or 8
    const int ty  = tid >> 4, tx = tid & 15;

    const float* Qp = Qh + (long)(z * 1024 + blockIdx.y * 128 + r) * 64 + dc;
    const float* Kp = Kh + (long)(z * 1024 + blockIdx.x * 128 + r) * 64 + dc;

    u64 acc2[8][4];
#pragma unroll
    for (int m = 0; m < 8; m++)
#pragma unroll
        for (int n = 0; n < 4; n++) acc2[m][n] = 0ULL;

    for (int kt = 0; kt < 4; kt++) {
        const float4 q0 = *(const float4*)(Qp + kt * 16);
        const float4 q1 = *(const float4*)(Qp + kt * 16 + 4);
        const float4 k0 = *(const float4*)(Kp + kt * 16);
        const float4 k1 = *(const float4*)(Kp + kt * 16 + 4);
        if (kt) __syncthreads();
        float qv[8] = {q0.x, q0.y, q0.z, q0.w, q1.x, q1.y, q1.z, q1.w};
        float kv[8] = {k0.x, k0.y, k0.z, k0.w, k1.x, k1.y, k1.z, k1.w};
#pragma unroll
        for (int t = 0; t < 8; t++) {
            *(float2*)&Qs[dc + t][2 * r] = make_float2(qv[t], qv[t]);
            Ks[dc + t][r] = -kv[t];
        }
        __syncthreads();
#pragma unroll
        for (int k = 0; k < 16; k++) {
            u64 q2[8], k2[4];
#pragma unroll
            for (int m = 0; m < 8; m++)
                q2[m] = *(const u64*)&Qs[k][2 * (ty * 8 + m)];
            *(ulonglong2*)&k2[0] = *(const ulonglong2*)&Ks[k][tx * 8];
            *(ulonglong2*)&k2[2] = *(const ulonglong2*)&Ks[k][tx * 8 + 4];
#pragma unroll
            for (int m = 0; m < 8; m++)
#pragma unroll
                for (int n = 0; n < 4; n++) {
                    const u64 t2 = abs2(add2(q2[m], k2[n]));
                    acc2[m][n] = add2(acc2[m][n], t2);
                }
        }
    }

    const long base = ((long)(z * 1024 + blockIdx.y * 128 + ty * 8)) * 1024
                    + blockIdx.x * 128 + tx * 8;
#pragma unroll
    for (int m = 0; m < 8; m++) {
        float o[8];
#pragma unroll
        for (int n = 0; n < 4; n++) {
            float lo, hi;
            unpk2(lo, hi, acc2[m][n]);
            o[2 * n]     = __expf(-0.5f * lo * lo);
            o[2 * n + 1] = __expf(-0.5f * hi * hi);
        }
        *(float4*)(E + base + (long)m * 1024 + 0) = make_float4(o[0], o[1], o[2], o[3]);
        *(float4*)(E + base + (long)m * 1024 + 4) = make_float4(o[4], o[5], o[6], o[7]);
    }
}

// ---------------------------------------------------------------------------
// Phase A2: rdenom[b][j][i] = 1 / sum_h E[b*8+h][j][i]   (float4 vectorized)
// ---------------------------------------------------------------------------
__global__ __launch_bounds__(256) void denom_kernel(
    const float* __restrict__ E, float* __restrict__ rd)
{
    const int gid = blockIdx.x * 256 + threadIdx.x;  // 1048576 float4s
    const int b   = gid >> 18;
    const int rem = gid & ((1 << 18) - 1);
    const float4* Ep = (const float4*)E;
    float4 s = make_float4(0.f, 0.f, 0.f, 0.f);
#pragma unroll
    for (int h = 0; h < 8; h++) {
        const float4 v = Ep[(((long)(b * 8 + h)) << 18) + rem];
        s.x += v.x; s.y += v.y; s.z += v.z; s.w += v.w;
    }
    ((float4*)rd)[gid] = make_float4(1.f / s.x, 1.f / s.y, 1.f / s.z, 1.f / s.w);
}

// ---------------------------------------------------------------------------
// Phase B: out[b][j][d*8+h] = sum_i (E[z][j][i]*rd[b][j][i]) * V[z][i][d]
// f32x2 packed over j-pairs (contiguous in As), V scalar duplicated.
// ---------------------------------------------------------------------------
__global__ __launch_bounds__(256) void attn_v_x2(
    const float* __restrict__ E, const float* __restrict__ rd,
    const float* __restrict__ Vh, float* __restrict__ Oo)
{
    __shared__ float As[16][128];
    __shared__ float Vs[16][64];

    const int z = blockIdx.z, b = z >> 3, h = z & 7;
    const int tid = threadIdx.x;
    const int ar = tid >> 1, ac = (tid & 1) << 3;     // A: j-row, i-col base
    const int vr = tid >> 4, vc = (tid & 15) << 2;    // V: i-row, d-col
    const int ty = tid >> 4, tx = tid & 15;

    const float* Ep = E  + ((long)(z * 1024 + blockIdx.y * 128 + ar)) * 1024 + ac;
    const float* Rp = rd + ((long)(b * 1024 + blockIdx.y * 128 + ar)) * 1024 + ac;
    const float* Vp = Vh + (long)(z * 1024 + vr) * 64 + vc;

    u64 acc2[4][4];   // [j-pair][d]
#pragma unroll
    for (int m = 0; m < 4; m++)
#pragma unroll
        for (int n = 0; n < 4; n++) acc2[m][n] = 0ULL;

    for (int kt = 0; kt < 64; kt++) {
        const float4 e0 = *(const float4*)(Ep + kt * 16);
        const float4 e1 = *(const float4*)(Ep + kt * 16 + 4);
        const float4 r0 = *(const float4*)(Rp + kt * 16);
        const float4 r1 = *(const float4*)(Rp + kt * 16 + 4);
        const float4 v4 = *(const float4*)(Vp + (long)kt * 16 * 64);
        if (kt) __syncthreads();
        As[ac + 0][ar] = e0.x * r0.x; As[ac + 1][ar] = e0.y * r0.y;
        As[ac + 2][ar] = e0.z * r0.z; As[ac + 3][ar] = e0.w * r0.w;
        As[ac + 4][ar] = e1.x * r1.x; As[ac + 5][ar] = e1.y * r1.y;
        As[ac + 6][ar] = e1.z * r1.z; As[ac + 7][ar] = e1.w * r1.w;
        *(float4*)&Vs[vr][vc] = v4;
        __syncthreads();
#pragma unroll
        for (int k = 0; k < 16; k++) {
            u64 a2[4];
            float vf[4];
            *(ulonglong2*)&a2[0] = *(const ulonglong2*)&As[k][ty * 8];
            *(ulonglong2*)&a2[2] = *(const ulonglong2*)&As[k][ty * 8 + 4];
            *(float4*)&vf[0] = *(const float4*)&Vs[k][tx * 4];
#pragma unroll
            for (int n = 0; n < 4; n++) {
                const u64 v2 = dup2(vf[n]);
#pragma unroll
                for (int m = 0; m < 4; m++) ffma2(acc2[m][n], a2[m], v2);
            }
        }
    }

    const int j0 = blockIdx.y * 128 + ty * 8;
#pragma unroll
    for (int m = 0; m < 4; m++) {
        float* op0 = Oo + (long)(b * 1024 + j0 + 2 * m) * 512 + h;
        float* op1 = Oo + (long)(b * 1024 + j0 + 2 * m + 1) * 512 + h;
#pragma unroll
        for (int n = 0; n < 4; n++) {
            float lo, hi;
            unpk2(lo, hi, acc2[m][n]);
            op0[(tx * 4 + n) * 8] = lo;
            op1[(tx * 4 + n) * 8] = hi;
        }
    }
}

// ---------------------------------------------------------------------------
extern "C" void kernel_launch(void* const* d_in, const int* in_sizes, int n_in,
                              void* d_out, int out_size)
{
    const float* KEY   = (const float*)d_in[0];
    const float* VALUE = (const float*)d_in[1];
    const float* QUERY = (const float*)d_in[2];

    float *buf1, *buf2, *Kh, *Qh, *Vh, *E, *rd, *attn;
    cudaGetSymbolAddress((void**)&buf1, g_buf1);
    cudaGetSymbolAddress((void**)&buf2, g_buf2);
    cudaGetSymbolAddress((void**)&Kh,   g_Kh);
    cudaGetSymbolAddress((void**)&Qh,   g_Qh);
    cudaGetSymbolAddress((void**)&Vh,   g_Vh);
    cudaGetSymbolAddress((void**)&E,    g_E);
    cudaGetSymbolAddress((void**)&rd,   g_rd);
    cudaGetSymbolAddress((void**)&attn, g_attn);

    const dim3 blk(256);
    const dim3 gm(HH / 128, ROWS / 128);   // (4, 32)

    auto run_mlp = [&](const float* in, int base, float* out) {
        sgemm_bias_x2<<<gm, blk>>>(in,   (const float*)d_in[base + 0],
                                   (const float*)d_in[base + 1], buf1, ROWS, HH, F, 1, 0);
        sgemm_bias_x2<<<gm, blk>>>(buf1, (const float*)d_in[base + 2],
                                   (const float*)d_in[base + 3], buf2, ROWS, HH, HH, 1, 0);
        sgemm_bias_x2<<<gm, blk>>>(buf2, (const float*)d_in[base + 4],
                                   (const float*)d_in[base + 5], out, ROWS, HH, HH, 0, 1);
    };

    run_mlp(KEY,   3,  Kh);
    run_mlp(QUERY, 9,  Qh);
    run_mlp(VALUE, 15, Vh);

    dist_exp_x2<<<dim3(8, 8, 32), blk>>>(Qh, Kh, E);
    denom_kernel<<<4096, blk>>>(E, rd);
    attn_v_x2<<<dim3(1, 8, 32), blk>>>(E, rd, Vh, attn);

    sgemm_bias_x2<<<dim3(OO / 128, ROWS / 128), blk>>>(
        attn, (const float*)d_in[21], (const float*)d_in[22],
        (float*)d_out, ROWS, OO, HH, 0, 0);
}